// round 13
// baseline (speedup 1.0000x reference)
#include <cuda_runtime.h>
#include <math.h>

#define NB 4096
#define NC 256
#define GRID 912   // 6 blocks/SM x 152 SMs, uniform residency (regs<=42)

// One full Heisenberg evaluation from an x-vector and register-resident coefs.
__device__ __forceinline__ float4 eval_sim(const float4 xv, const float4 kw,
                                           const float4 k2, const float4 k3,
                                           const float4 k4) {
    const float t0 = xv.x + kw.x;
    const float t1 = xv.y + kw.y;
    const float t2 = xv.z + kw.z;
    const float t3 = xv.w + kw.w;
    const float S0 = __sinf(t0), C0 = __cosf(t0);
    const float S1 = __sinf(t1), C1 = __cosf(t1);
    const float S2 = __sinf(t2), C2 = __cosf(t2);
    const float S3 = __sinf(t3), C3 = __cosf(t3);

    const float C1C3 = C1 * C3;
    const float S1S3 = S1 * S3;
    const float C0C2 = C0 * C2;
    const float S0S2 = S0 * S2;
    const float C0S2 = C0 * S2;
    const float S0C2 = S0 * C2;

    // <Z0> = A0*C0C1C3 + B0*S0S1S3 + E0*C0S1S3 + F0*S0C1C3
    float o0 = k2.x * (C0 * C1C3);
    o0 = fmaf(k2.y, S0 * S1S3, o0);
    o0 = fmaf(k2.z, C0 * S1S3, o0);
    o0 = fmaf(k2.w, S0 * C1C3, o0);

    // <Z1> = A1*C0C2C3 + B1*S0S2C3
    float o1 = k3.x * (C0C2 * C3);
    o1 = fmaf(k3.y, S0S2 * C3, o1);

    // <Z2> = A2*C1C3 + B2*S1S3
    const float o2 = fmaf(k3.z, C1C3, k3.w * S1S3);

    // <Z3> = A3*C0C2 + B3*S0S2 + E3*C0S2 + F3*S0C2
    float o3 = k4.x * C0C2;
    o3 = fmaf(k4.y, S0S2, o3);
    o3 = fmaf(k4.z, C0S2, o3);
    o3 = fmaf(k4.w, S0C2, o3);

    float4 o;
    o.x = o0; o.y = o1; o.z = o2; o.w = o3;
    return o;
}

__global__ void __launch_bounds__(256, 6)
qsim12_kernel(const float4* __restrict__ x4, const float4* __restrict__ w4,
              float4* __restrict__ out4) {
    const int c = threadIdx.x;         // circuit

    // Coefficient loads first (latency overlaps the first x loads below).
    const float4 kw = w4[2 * c];        // w0 angles (layer 1) -> merged into Theta
    const float4 w1 = w4[2 * c + 1];    // w1 angles (layer 2)

    // Depth-2 pipeline warm-up: two rows in flight.
    int b = blockIdx.x;
    float4 cur = x4[b * NC + c];
    const int b1 = b + GRID;
    float4 nxt;
    if (b1 < NB) nxt = x4[b1 * NC + c];

    // Analytic Heisenberg coefficients: products of full-angle cos/sin(w1_q).
    const float c0 = __cosf(w1.x), s0 = __sinf(w1.x);
    const float c1 = __cosf(w1.y), s1 = __sinf(w1.y);
    const float c2 = __cosf(w1.z), s2 = __sinf(w1.z);
    const float c3 = __cosf(w1.w), s3 = __sinf(w1.w);

    const float c1c2 = c1 * c2;
    const float s1s2 = s1 * s2;
    const float c2c3 = c2 * c3;
    const float s2s3 = s2 * s3;

    float4 k2, k3, k4;
    k2.x = c1c2 * c3;        // A0
    k2.y = c1c2 * s3;        // B0
    k2.z = s1s2 * c3;        // E0
    k2.w = s1s2 * s3;        // F0
    k3.x = c0 * c1;          // A1
    k3.y = s0 * s1;          // B1
    k3.z = c0 * c1c2;        // A2
    k3.w = c0 * s1s2;        // B2
    k4.x = k3.z * c3;        // A3 = c0c1c2c3
    k4.y = k3.y * c2c3;      // B3 = s0s1c2c3
    k4.z = (s0 * c1) * s2s3; // E3 = s0c1s2s3
    k4.w = k3.w * s3;        // F3 = c0s1s2s3

    // Persistent grid-stride, two rows in flight (prefetch r+2G while computing r).
#pragma unroll 1
    while (b < NB) {
        const int b2 = b + 2 * GRID;
        float4 nn;
        if (b2 < NB) nn = x4[b2 * NC + c];
        out4[b * NC + c] = eval_sim(cur, kw, k2, k3, k4);
        cur = nxt;
        nxt = nn;
        b += GRID;
    }
}

extern "C" void kernel_launch(void* const* d_in, const int* in_sizes, int n_in,
                              void* d_out, int out_size) {
    const float* x = (const float*)d_in[0];        // (4096, 1024)
    const float* w = (const float*)d_in[1];        // (256, 2, 4)
    float* out = (float*)d_out;                    // (4096, 1024)

    qsim12_kernel<<<GRID, 256>>>(reinterpret_cast<const float4*>(x),
                                 reinterpret_cast<const float4*>(w),
                                 reinterpret_cast<float4*>(out));
}

// round 14
// speedup vs baseline: 1.0258x; 1.0258x over previous
#include <cuda_runtime.h>
#include <math.h>

#define NB 4096
#define NC 256
#define GRID 456              // 3 blocks/SM x 152 SMs, uniform residency
#define STR (GRID * NC)       // float4 stride between this thread's rows

// One full Heisenberg evaluation from an x-vector and register-resident coefs.
__device__ __forceinline__ float4 eval_sim(const float4 xv, const float4 kw,
                                           const float4 k2, const float4 k3,
                                           const float4 k4) {
    const float t0 = xv.x + kw.x;
    const float t1 = xv.y + kw.y;
    const float t2 = xv.z + kw.z;
    const float t3 = xv.w + kw.w;
    const float S0 = __sinf(t0), C0 = __cosf(t0);
    const float S1 = __sinf(t1), C1 = __cosf(t1);
    const float S2 = __sinf(t2), C2 = __cosf(t2);
    const float S3 = __sinf(t3), C3 = __cosf(t3);

    const float C1C3 = C1 * C3;
    const float S1S3 = S1 * S3;
    const float C0C2 = C0 * C2;
    const float S0S2 = S0 * S2;
    const float C0S2 = C0 * S2;
    const float S0C2 = S0 * C2;

    // <Z0> = C0*(A0*C1C3 + E0*S1S3) + S0*(B0*S1S3 + F0*C1C3)   (6 ops)
    const float u0 = fmaf(k2.z, S1S3, k2.x * C1C3);
    const float v0 = fmaf(k2.w, C1C3, k2.y * S1S3);
    const float o0 = fmaf(S0, v0, C0 * u0);

    // <Z1> = C3*(A1*C0C2 + B1*S0S2)
    const float o1 = C3 * fmaf(k3.y, S0S2, k3.x * C0C2);

    // <Z2> = A2*C1C3 + B2*S1S3
    const float o2 = fmaf(k3.z, C1C3, k3.w * S1S3);

    // <Z3> = A3*C0C2 + B3*S0S2 + E3*C0S2 + F3*S0C2
    float o3 = k4.x * C0C2;
    o3 = fmaf(k4.y, S0S2, o3);
    o3 = fmaf(k4.z, C0S2, o3);
    o3 = fmaf(k4.w, S0C2, o3);

    float4 o;
    o.x = o0; o.y = o1; o.z = o2; o.w = o3;
    return o;
}

__global__ void __launch_bounds__(256, 3)
qsim13_kernel(const float4* __restrict__ x4, const float4* __restrict__ w4,
              float4* __restrict__ out4) {
    const int c = threadIdx.x;          // circuit
    const int b = blockIdx.x;           // 0..455

    // Coefficient loads first (latency overlaps the first x loads below).
    const float4 kw = w4[2 * c];        // w0 angles (layer 1) -> merged into Theta
    const float4 w1 = w4[2 * c + 1];    // w1 angles (layer 2)

    // Rows for this block: b, b+GRID, ... ; niter = 9 for b<448, else 8.
    const int niter = (NB - b + GRID - 1) / GRID;
    const float4* xp = x4 + (b * NC + c);
    float4* op = out4 + (b * NC + c);

    // Depth-2 pipeline warm-up: two rows in flight.
    float4 cur = xp[0];
    float4 nxt;
    if (niter > 1) nxt = xp[STR];

    // Analytic Heisenberg coefficients: products of full-angle cos/sin(w1_q).
    const float c0 = __cosf(w1.x), s0 = __sinf(w1.x);
    const float c1 = __cosf(w1.y), s1 = __sinf(w1.y);
    const float c2 = __cosf(w1.z), s2 = __sinf(w1.z);
    const float c3 = __cosf(w1.w), s3 = __sinf(w1.w);

    const float c1c2 = c1 * c2;
    const float s1s2 = s1 * s2;
    const float c2c3 = c2 * c3;
    const float s2s3 = s2 * s3;

    float4 k2, k3, k4;
    k2.x = c1c2 * c3;        // A0
    k2.y = c1c2 * s3;        // B0
    k2.z = s1s2 * c3;        // E0
    k2.w = s1s2 * s3;        // F0
    k3.x = c0 * c1;          // A1
    k3.y = s0 * s1;          // B1
    k3.z = c0 * c1c2;        // A2
    k3.w = c0 * s1s2;        // B2
    k4.x = k3.z * c3;        // A3 = c0c1c2c3
    k4.y = k3.y * c2c3;      // B3 = s0s1c2c3
    k4.z = (s0 * c1) * s2s3; // E3 = s0c1s2s3
    k4.w = k3.w * s3;        // F3 = c0s1s2s3

    // Steady state: pointers advance by IADD only; prefetch 2 rows ahead.
#pragma unroll 1
    for (int i = 0; i < niter; ++i) {
        float4 nn;
        if (i + 2 < niter) nn = xp[2 * STR];
        op[0] = eval_sim(cur, kw, k2, k3, k4);
        cur = nxt;
        nxt = nn;
        xp += STR;
        op += STR;
    }
}

extern "C" void kernel_launch(void* const* d_in, const int* in_sizes, int n_in,
                              void* d_out, int out_size) {
    const float* x = (const float*)d_in[0];        // (4096, 1024)
    const float* w = (const float*)d_in[1];        // (256, 2, 4)
    float* out = (float*)d_out;                    // (4096, 1024)

    qsim13_kernel<<<GRID, 256>>>(reinterpret_cast<const float4*>(x),
                                 reinterpret_cast<const float4*>(w),
                                 reinterpret_cast<float4*>(out));
}